// round 1
// baseline (speedup 1.0000x reference)
#include <cuda_runtime.h>

#define Dd 256
#define HWc 1024
#define Kc 1024
#define NBLK 512

__device__ float g_cn[Kc];
__device__ float g_cbT[Dd * Kc];   // transposed codebook: [d][k]
__device__ float g_partials[NBLK];

#define PACK2(out, lo, hi) \
    asm("mov.b64 %0, {%1, %2};" : "=l"(out) : "r"(__float_as_uint(lo)), "r"(__float_as_uint(hi)))
#define FMA2(d, a, b, c) \
    asm("fma.rn.f32x2 %0, %1, %2, %3;" : "=l"(d) : "l"(a), "l"(b), "l"(c))
#define UNPACK2(lo, hi, in) \
    asm("mov.b64 {%0, %1}, %2;" : "=r"(lo), "=r"(hi) : "l"(in))

// ---------------------------------------------------------------------------
// Kernel 1: codebook transpose + per-code squared norms
// grid = 1024 blocks (one per code), 256 threads (one per dim)
// ---------------------------------------------------------------------------
__global__ void prep_kernel(const float* __restrict__ cb) {
    __shared__ float red[256];
    int k = blockIdx.x, t = threadIdx.x;
    float v = cb[k * Dd + t];
    g_cbT[t * Kc + k] = v;
    red[t] = v * v;
    __syncthreads();
    for (int s = 128; s > 0; s >>= 1) {
        if (t < s) red[t] += red[t + s];
        __syncthreads();
    }
    if (t == 0) g_cn[k] = red[0];
}

// ---------------------------------------------------------------------------
// Kernel 2: distance GEMM + argmin + gather + outputs + per-block loss partial
// grid = 512 blocks (each: 128 queries x all 1024 codes), 256 threads
// ---------------------------------------------------------------------------
__global__ __launch_bounds__(256)
void vq_kernel(const float* __restrict__ z, const float* __restrict__ cb,
               float* __restrict__ out) {
    __shared__ float zt[32][128];   // [d][m]
    __shared__ float ct[32][128];   // [d][j]
    __shared__ float zz_s[128];
    __shared__ int   idx_s[128];
    __shared__ float red[256];

    const int t  = threadIdx.x;
    const int tx = t & 15;          // code-tile coordinate
    const int ty = t >> 4;          // query-tile coordinate
    const int bb = blockIdx.x;
    const int b  = bb >> 3;
    const int hw0 = (bb & 7) << 7;
    const float* zb = z + ((size_t)b * Dd) * HWc + hw0;   // element (d,m) at zb[d*HWc+m]

    // ---- query squared norms (2 threads per query) ----
    {
        int m = t & 127, half = t >> 7;
        const float* p = zb + (size_t)(half * 128) * HWc + m;
        float s = 0.f;
        #pragma unroll 8
        for (int d = 0; d < 128; d++) { float v = p[(size_t)d * HWc]; s = fmaf(v, v, s); }
        red[t] = s;
        __syncthreads();
        if (t < 128) zz_s[t] = red[t] + red[t + 128];
        __syncthreads();
    }

    float zz_r[8];
    #pragma unroll
    for (int i = 0; i < 8; i++) {
        int m = (i < 4) ? (4 * ty + i) : (64 + 4 * ty + (i - 4));
        zz_r[i] = zz_s[m];
    }

    float bestd[8];
    int   besti[8];
    #pragma unroll
    for (int i = 0; i < 8; i++) { bestd[i] = 3.4e38f; besti[i] = 0; }

    // ---- loop over code chunks of 128 ----
    for (int k0 = 0; k0 < Kc; k0 += 128) {
        unsigned long long acc[8][4];
        #pragma unroll
        for (int i = 0; i < 8; i++)
            #pragma unroll
            for (int j = 0; j < 4; j++) acc[i][j] = 0ull;

        // prefetch first D-chunk into registers
        float4 rz[4], rc[4];
        #pragma unroll
        for (int it = 0; it < 4; it++) {
            int lin = it * 256 + t;
            int dd = lin >> 5, c4 = lin & 31;
            rz[it] = *(const float4*)(zb + (size_t)dd * HWc + 4 * c4);
            rc[it] = *(const float4*)(g_cbT + (size_t)dd * Kc + k0 + 4 * c4);
        }

        for (int d0 = 0; d0 < Dd; d0 += 32) {
            #pragma unroll
            for (int it = 0; it < 4; it++) {
                int lin = it * 256 + t;
                int dd = lin >> 5, c4 = lin & 31;
                *(float4*)&zt[dd][4 * c4] = rz[it];
                *(float4*)&ct[dd][4 * c4] = rc[it];
            }
            __syncthreads();
            if (d0 + 32 < Dd) {
                #pragma unroll
                for (int it = 0; it < 4; it++) {
                    int lin = it * 256 + t;
                    int dd = lin >> 5, c4 = lin & 31;
                    rz[it] = *(const float4*)(zb + (size_t)(d0 + 32 + dd) * HWc + 4 * c4);
                    rc[it] = *(const float4*)(g_cbT + (size_t)(d0 + 32 + dd) * Kc + k0 + 4 * c4);
                }
            }
            #pragma unroll 4
            for (int kk = 0; kk < 32; kk++) {
                float4 a0 = *(const float4*)&zt[kk][4 * ty];
                float4 a1 = *(const float4*)&zt[kk][64 + 4 * ty];
                float4 b0 = *(const float4*)&ct[kk][4 * tx];
                float4 b1 = *(const float4*)&ct[kk][64 + 4 * tx];
                unsigned long long bp0, bp1, bp2, bp3;
                PACK2(bp0, b0.x, b0.y); PACK2(bp1, b0.z, b0.w);
                PACK2(bp2, b1.x, b1.y); PACK2(bp3, b1.z, b1.w);
                float av[8] = {a0.x, a0.y, a0.z, a0.w, a1.x, a1.y, a1.z, a1.w};
                #pragma unroll
                for (int i = 0; i < 8; i++) {
                    unsigned long long as_;
                    PACK2(as_, av[i], av[i]);
                    FMA2(acc[i][0], as_, bp0, acc[i][0]);
                    FMA2(acc[i][1], as_, bp1, acc[i][1]);
                    FMA2(acc[i][2], as_, bp2, acc[i][2]);
                    FMA2(acc[i][3], as_, bp3, acc[i][3]);
                }
            }
            __syncthreads();
        }

        // chunk epilogue: distances + running argmin (ascending j => first-min wins)
        #pragma unroll
        for (int i = 0; i < 8; i++) {
            #pragma unroll
            for (int jp = 0; jp < 4; jp++) {
                unsigned u0, u1;
                UNPACK2(u0, u1, acc[i][jp]);
                float dt0 = __uint_as_float(u0), dt1 = __uint_as_float(u1);
                int col = (jp < 2) ? (4 * tx + 2 * jp) : (64 + 4 * tx + 2 * (jp - 2));
                int j0 = k0 + col;
                // replicate reference rounding: (zz + cn) rounded, then -2*dot (exact *2)
                float s0 = zz_r[i] + g_cn[j0];
                float s1 = zz_r[i] + g_cn[j0 + 1];
                float dist0 = fmaf(-2.f, dt0, s0);
                float dist1 = fmaf(-2.f, dt1, s1);
                if (dist0 < bestd[i]) { bestd[i] = dist0; besti[i] = j0; }
                if (dist1 < bestd[i]) { bestd[i] = dist1; besti[i] = j0 + 1; }
            }
        }
    }

    // ---- argmin reduce across the 16 tx-lanes holding each query row ----
    #pragma unroll
    for (int i = 0; i < 8; i++) {
        float d = bestd[i]; int ix = besti[i];
        #pragma unroll
        for (int w = 1; w <= 8; w <<= 1) {
            float od = __shfl_xor_sync(0xffffffffu, d, w);
            int   oi = __shfl_xor_sync(0xffffffffu, ix, w);
            if (od < d || (od == d && oi < ix)) { d = od; ix = oi; }
        }
        if (tx == 0) {
            int m = (i < 4) ? (4 * ty + i) : (64 + 4 * ty + (i - 4));
            idx_s[m] = ix;
        }
    }
    __syncthreads();

    // ---- outputs: quantized_st (= z + (q - z), reference rounding) + loss partial ----
    float* outq = out + ((size_t)b * Dd) * HWc + hw0;
    float lsum = 0.f;
    #pragma unroll 1
    for (int it = 0; it < 32; it++) {
        int lin = it * 256 + t;           // 8192 float4 positions: (d, c4)
        int d = lin >> 5, c4 = lin & 31;
        int m0 = 4 * c4;
        float4 zv = *(const float4*)(zb + (size_t)d * HWc + m0);
        float q0 = cb[(size_t)idx_s[m0 + 0] * Dd + d];
        float q1 = cb[(size_t)idx_s[m0 + 1] * Dd + d];
        float q2 = cb[(size_t)idx_s[m0 + 2] * Dd + d];
        float q3 = cb[(size_t)idx_s[m0 + 3] * Dd + d];
        float f0 = q0 - zv.x, f1 = q1 - zv.y, f2 = q2 - zv.z, f3 = q3 - zv.w;
        float4 ov = make_float4(zv.x + f0, zv.y + f1, zv.z + f2, zv.w + f3);
        *(float4*)(outq + (size_t)d * HWc + m0) = ov;
        lsum += f0 * f0 + f1 * f1 + f2 * f2 + f3 * f3;
    }

    // indices output (as float, exact for 0..1023)
    if (t < 128) out[16777216 + (size_t)b * 1024 + hw0 + t] = (float)idx_s[t];

    // deterministic per-block loss partial
    red[t] = lsum;
    __syncthreads();
    for (int s = 128; s > 0; s >>= 1) { if (t < s) red[t] += red[t + s]; __syncthreads(); }
    if (t == 0) g_partials[bb] = red[0];
}

// ---------------------------------------------------------------------------
// Kernel 3: final loss reduction  loss = 0.25*S + 1.0*S
// ---------------------------------------------------------------------------
__global__ void loss_kernel(float* __restrict__ out) {
    __shared__ float red[NBLK];
    int t = threadIdx.x;
    red[t] = g_partials[t];
    __syncthreads();
    for (int s = 256; s > 0; s >>= 1) { if (t < s) red[t] += red[t + s]; __syncthreads(); }
    if (t == 0) { float S = red[0]; out[16842752] = S * 0.25f + S; }
}

extern "C" void kernel_launch(void* const* d_in, const int* in_sizes, int n_in,
                              void* d_out, int out_size) {
    const float* z  = (const float*)d_in[0];
    const float* cb = (const float*)d_in[1];
    if (n_in >= 2 && in_sizes[0] == Kc * Dd) {   // defensive: detect swapped order
        z  = (const float*)d_in[1];
        cb = (const float*)d_in[0];
    }
    float* out = (float*)d_out;
    prep_kernel<<<Kc, 256>>>(cb);
    vq_kernel<<<NBLK, 256>>>(z, cb, out);
    loss_kernel<<<1, NBLK>>>(out);
}

// round 2
// speedup vs baseline: 1.0006x; 1.0006x over previous
#include <cuda_runtime.h>

#define Dd 256
#define HWc 1024
#define Kc 1024
#define NBLK 512

__device__ float g_cn[Kc];
__device__ float g_cbT[Dd * Kc];   // transposed codebook: [d][k]
__device__ float g_partials[NBLK];

#define PACK2(out, lo, hi) \
    asm("mov.b64 %0, {%1, %2};" : "=l"(out) : "r"(__float_as_uint(lo)), "r"(__float_as_uint(hi)))
#define FMA2(d, a, b, c) \
    asm("fma.rn.f32x2 %0, %1, %2, %3;" : "=l"(d) : "l"(a), "l"(b), "l"(c))
#define UNPACK2(lo, hi, in) \
    asm("mov.b64 {%0, %1}, %2;" : "=r"(lo), "=r"(hi) : "l"(in))

// ---------------------------------------------------------------------------
// Kernel 1: codebook transpose + per-code squared norms
// grid = 1024 blocks (one per code), 256 threads (one per dim)
// ---------------------------------------------------------------------------
__global__ void prep_kernel(const float* __restrict__ cb) {
    __shared__ float red[256];
    int k = blockIdx.x, t = threadIdx.x;
    float v = cb[k * Dd + t];
    g_cbT[t * Kc + k] = v;
    red[t] = v * v;
    __syncthreads();
    for (int s = 128; s > 0; s >>= 1) {
        if (t < s) red[t] += red[t + s];
        __syncthreads();
    }
    if (t == 0) g_cn[k] = red[0];
}

// ---------------------------------------------------------------------------
// Kernel 2: distance GEMM + argmin + gather + outputs + per-block loss partial
// grid = 512 blocks (each: 128 queries x all 1024 codes), 256 threads
// ---------------------------------------------------------------------------
__global__ __launch_bounds__(256)
void vq_kernel(const float* __restrict__ z, const float* __restrict__ cb,
               float* __restrict__ out) {
    __shared__ float zt[32][128];   // [d][m]
    __shared__ float ct[32][128];   // [d][j]
    __shared__ float zz_s[128];
    __shared__ int   idx_s[128];
    __shared__ float red[256];

    const int t  = threadIdx.x;
    const int tx = t & 15;          // code-tile coordinate
    const int ty = t >> 4;          // query-tile coordinate
    const int bb = blockIdx.x;
    const int b  = bb >> 3;
    const int hw0 = (bb & 7) << 7;
    const float* zb = z + ((size_t)b * Dd) * HWc + hw0;   // element (d,m) at zb[d*HWc+m]

    // ---- query squared norms (2 threads per query) ----
    {
        int m = t & 127, half = t >> 7;
        const float* p = zb + (size_t)(half * 128) * HWc + m;
        float s = 0.f;
        #pragma unroll 8
        for (int d = 0; d < 128; d++) { float v = p[(size_t)d * HWc]; s = fmaf(v, v, s); }
        red[t] = s;
        __syncthreads();
        if (t < 128) zz_s[t] = red[t] + red[t + 128];
        __syncthreads();
    }

    float zz_r[8];
    #pragma unroll
    for (int i = 0; i < 8; i++) {
        int m = (i < 4) ? (4 * ty + i) : (64 + 4 * ty + (i - 4));
        zz_r[i] = zz_s[m];
    }

    float bestd[8];
    int   besti[8];
    #pragma unroll
    for (int i = 0; i < 8; i++) { bestd[i] = 3.4e38f; besti[i] = 0; }

    // ---- loop over code chunks of 128 ----
    for (int k0 = 0; k0 < Kc; k0 += 128) {
        unsigned long long acc[8][4];
        #pragma unroll
        for (int i = 0; i < 8; i++)
            #pragma unroll
            for (int j = 0; j < 4; j++) acc[i][j] = 0ull;

        // prefetch first D-chunk into registers
        float4 rz[4], rc[4];
        #pragma unroll
        for (int it = 0; it < 4; it++) {
            int lin = it * 256 + t;
            int dd = lin >> 5, c4 = lin & 31;
            rz[it] = *(const float4*)(zb + (size_t)dd * HWc + 4 * c4);
            rc[it] = *(const float4*)(g_cbT + (size_t)dd * Kc + k0 + 4 * c4);
        }

        for (int d0 = 0; d0 < Dd; d0 += 32) {
            #pragma unroll
            for (int it = 0; it < 4; it++) {
                int lin = it * 256 + t;
                int dd = lin >> 5, c4 = lin & 31;
                *(float4*)&zt[dd][4 * c4] = rz[it];
                *(float4*)&ct[dd][4 * c4] = rc[it];
            }
            __syncthreads();
            if (d0 + 32 < Dd) {
                #pragma unroll
                for (int it = 0; it < 4; it++) {
                    int lin = it * 256 + t;
                    int dd = lin >> 5, c4 = lin & 31;
                    rz[it] = *(const float4*)(zb + (size_t)(d0 + 32 + dd) * HWc + 4 * c4);
                    rc[it] = *(const float4*)(g_cbT + (size_t)(d0 + 32 + dd) * Kc + k0 + 4 * c4);
                }
            }
            #pragma unroll 4
            for (int kk = 0; kk < 32; kk++) {
                float4 a0 = *(const float4*)&zt[kk][4 * ty];
                float4 a1 = *(const float4*)&zt[kk][64 + 4 * ty];
                float4 b0 = *(const float4*)&ct[kk][4 * tx];
                float4 b1 = *(const float4*)&ct[kk][64 + 4 * tx];
                unsigned long long bp0, bp1, bp2, bp3;
                PACK2(bp0, b0.x, b0.y); PACK2(bp1, b0.z, b0.w);
                PACK2(bp2, b1.x, b1.y); PACK2(bp3, b1.z, b1.w);
                float av[8] = {a0.x, a0.y, a0.z, a0.w, a1.x, a1.y, a1.z, a1.w};
                #pragma unroll
                for (int i = 0; i < 8; i++) {
                    unsigned long long as_;
                    PACK2(as_, av[i], av[i]);
                    FMA2(acc[i][0], as_, bp0, acc[i][0]);
                    FMA2(acc[i][1], as_, bp1, acc[i][1]);
                    FMA2(acc[i][2], as_, bp2, acc[i][2]);
                    FMA2(acc[i][3], as_, bp3, acc[i][3]);
                }
            }
            __syncthreads();
        }

        // chunk epilogue: distances + running argmin (ascending j => first-min wins)
        #pragma unroll
        for (int i = 0; i < 8; i++) {
            #pragma unroll
            for (int jp = 0; jp < 4; jp++) {
                unsigned u0, u1;
                UNPACK2(u0, u1, acc[i][jp]);
                float dt0 = __uint_as_float(u0), dt1 = __uint_as_float(u1);
                int col = (jp < 2) ? (4 * tx + 2 * jp) : (64 + 4 * tx + 2 * (jp - 2));
                int j0 = k0 + col;
                // replicate reference rounding: (zz + cn) rounded, then -2*dot (exact *2)
                float s0 = zz_r[i] + g_cn[j0];
                float s1 = zz_r[i] + g_cn[j0 + 1];
                float dist0 = fmaf(-2.f, dt0, s0);
                float dist1 = fmaf(-2.f, dt1, s1);
                if (dist0 < bestd[i]) { bestd[i] = dist0; besti[i] = j0; }
                if (dist1 < bestd[i]) { bestd[i] = dist1; besti[i] = j0 + 1; }
            }
        }
    }

    // ---- argmin reduce across the 16 tx-lanes holding each query row ----
    #pragma unroll
    for (int i = 0; i < 8; i++) {
        float d = bestd[i]; int ix = besti[i];
        #pragma unroll
        for (int w = 1; w <= 8; w <<= 1) {
            float od = __shfl_xor_sync(0xffffffffu, d, w);
            int   oi = __shfl_xor_sync(0xffffffffu, ix, w);
            if (od < d || (od == d && oi < ix)) { d = od; ix = oi; }
        }
        if (tx == 0) {
            int m = (i < 4) ? (4 * ty + i) : (64 + 4 * ty + (i - 4));
            idx_s[m] = ix;
        }
    }
    __syncthreads();

    // ---- outputs: quantized_st (= z + (q - z), reference rounding) + loss partial ----
    float* outq = out + ((size_t)b * Dd) * HWc + hw0;
    float lsum = 0.f;
    #pragma unroll 1
    for (int it = 0; it < 32; it++) {
        int lin = it * 256 + t;           // 8192 float4 positions: (d, c4)
        int d = lin >> 5, c4 = lin & 31;
        int m0 = 4 * c4;
        float4 zv = *(const float4*)(zb + (size_t)d * HWc + m0);
        float q0 = cb[(size_t)idx_s[m0 + 0] * Dd + d];
        float q1 = cb[(size_t)idx_s[m0 + 1] * Dd + d];
        float q2 = cb[(size_t)idx_s[m0 + 2] * Dd + d];
        float q3 = cb[(size_t)idx_s[m0 + 3] * Dd + d];
        float f0 = q0 - zv.x, f1 = q1 - zv.y, f2 = q2 - zv.z, f3 = q3 - zv.w;
        float4 ov = make_float4(zv.x + f0, zv.y + f1, zv.z + f2, zv.w + f3);
        *(float4*)(outq + (size_t)d * HWc + m0) = ov;
        lsum += f0 * f0 + f1 * f1 + f2 * f2 + f3 * f3;
    }

    // indices output (as float, exact for 0..1023)
    if (t < 128) out[16777216 + (size_t)b * 1024 + hw0 + t] = (float)idx_s[t];

    // deterministic per-block loss partial
    red[t] = lsum;
    __syncthreads();
    for (int s = 128; s > 0; s >>= 1) { if (t < s) red[t] += red[t + s]; __syncthreads(); }
    if (t == 0) g_partials[bb] = red[0];
}

// ---------------------------------------------------------------------------
// Kernel 3: final loss reduction  loss = 0.25*S + 1.0*S
// ---------------------------------------------------------------------------
__global__ void loss_kernel(float* __restrict__ out) {
    __shared__ float red[NBLK];
    int t = threadIdx.x;
    red[t] = g_partials[t];
    __syncthreads();
    for (int s = 256; s > 0; s >>= 1) { if (t < s) red[t] += red[t + s]; __syncthreads(); }
    if (t == 0) { float S = red[0]; out[16842752] = S * 0.25f + S; }
}

extern "C" void kernel_launch(void* const* d_in, const int* in_sizes, int n_in,
                              void* d_out, int out_size) {
    const float* z  = (const float*)d_in[0];
    const float* cb = (const float*)d_in[1];
    if (n_in >= 2 && in_sizes[0] == Kc * Dd) {   // defensive: detect swapped order
        z  = (const float*)d_in[1];
        cb = (const float*)d_in[0];
    }
    float* out = (float*)d_out;
    prep_kernel<<<Kc, 256>>>(cb);
    vq_kernel<<<NBLK, 256>>>(z, cb, out);
    loss_kernel<<<1, NBLK>>>(out);
}